// round 1
// baseline (speedup 1.0000x reference)
#include <cuda_runtime.h>

// ---------------------------------------------------------------------------
// Triaffine:  out[n,i,j] = sum_{c,d} (h1[nic] * A[nijc]) * W3[c,d] * (h2[nid] * B[nijd])
//   A[nijc] = sum_{a,b} l1[nia] W1[abc] l2[njb]   (l1/l2 = [layer, ones])
//   B likewise with W2.
// Staged as 3 GEMM passes through __device__ scratch + a final fused
// GEMM+reduce. All fp32, inner loops use packed fma.rn.f32x2 (2x FFMA rate).
// ---------------------------------------------------------------------------

#define BM 128
#define BN 128
#define BK 8
#define TM 8
#define TNH 4   // TN/2 packed pairs (TN = 8)

// Scratch (module-load allocated; no runtime alloc)
__device__ __align__(16) float g_X1[2048ull * 257 * 256];   // 539 MB
__device__ __align__(16) float g_X2[2048ull * 257 * 256];   // 539 MB
__device__ __align__(16) float g_A [2048ull * 256 * 256];   // 537 MB
__device__ __align__(16) float g_B [2048ull * 256 * 256];   // 537 MB
__device__ __align__(16) float g_W3T[256 * 256];

// ---------------------------------------------------------------------------
// Inner 128x128 micro-tile step over BK k-slices.
// As2: [BK][2*BM] with every A value duplicated (so LDS.64 -> packed (a,a)).
// Bs : [BK][BN].
// ---------------------------------------------------------------------------
__device__ __forceinline__ void mm_tile(unsigned long long acc[TM][TNH],
                                        const float* __restrict__ As2,
                                        const float* __restrict__ Bs,
                                        int ty, int tx)
{
#pragma unroll
    for (int kk = 0; kk < BK; ++kk) {
        unsigned long long a[TM], b[TNH];
        const float* ar = As2 + kk * (2 * BM) + 2 * (ty * TM);
        const float* br = Bs + kk * BN + tx * 8;
#pragma unroll
        for (int u = 0; u < TM; ++u)
            a[u] = *reinterpret_cast<const unsigned long long*>(ar + 2 * u);
#pragma unroll
        for (int v = 0; v < TNH; ++v)
            b[v] = *reinterpret_cast<const unsigned long long*>(br + 2 * v);
#pragma unroll
        for (int u = 0; u < TM; ++u)
#pragma unroll
            for (int v = 0; v < TNH; ++v)
                asm("fma.rn.f32x2 %0, %1, %2, %0;"
                    : "+l"(acc[u][v]) : "l"(a[u]), "l"(b[v]));
    }
}

// ---------------------------------------------------------------------------
// K0: transpose W3 -> g_W3T  (so the final GEMM reads it row-major)
// ---------------------------------------------------------------------------
__global__ void k_transpose(const float* __restrict__ W3)
{
    __shared__ float t[32][33];
    int bx = blockIdx.x * 32, by = blockIdx.y * 32;
    t[threadIdx.y][threadIdx.x] = W3[(size_t)(by + threadIdx.y) * 256 + bx + threadIdx.x];
    __syncthreads();
    g_W3T[(size_t)(bx + threadIdx.y) * 256 + by + threadIdx.x] = t[threadIdx.x][threadIdx.y];
}

// ---------------------------------------------------------------------------
// K1: X{1,2}[(n,i)][b*256+c] = sum_a l1p[(n,i),a] * W{1,2}[a][b*256+c]
//     GEMM M=2048, K=257, N=65792.  grid (514, 16, 2)
// ---------------------------------------------------------------------------
__global__ void __launch_bounds__(256, 2)
k_gemm1(const float* __restrict__ layer1,
        const float* __restrict__ W1,
        const float* __restrict__ W2)
{
    const int tid = threadIdx.x;
    const int ty = tid >> 4, tx = tid & 15;
    const int nBase = blockIdx.x * BN;
    const int mBase = blockIdx.y * BM;
    const float* __restrict__ W = blockIdx.z ? W2 : W1;
    float* __restrict__ X = blockIdx.z ? g_X2 : g_X1;

    __shared__ float As2[2][BK][2 * BM];
    __shared__ float Bs[2][BK][BN];

    const int ar  = tid >> 1;           // A row within tile (0..127)
    const int akq = (tid & 1) * 4;      // A k-quad offset
    const int bkk = tid >> 5;           // B k row (0..7)
    const int bcq = (tid & 31) * 4;     // B col quad

    const int K = 257;
    const int NIT = (K + BK - 1) / BK;  // 33

    float va[4];
    float4 vb;

    auto loadG = [&](int k0) {
        int k = k0 + akq;
        int mrow = mBase + ar;
        if (k + 3 < 256) {
            float4 f = *reinterpret_cast<const float4*>(layer1 + (size_t)mrow * 256 + k);
            va[0] = f.x; va[1] = f.y; va[2] = f.z; va[3] = f.w;
        } else {
#pragma unroll
            for (int j = 0; j < 4; ++j) {
                int kj = k + j;
                va[j] = (kj < 256) ? layer1[(size_t)mrow * 256 + kj]
                                   : (kj == 256 ? 1.0f : 0.0f);
            }
        }
        int kb = k0 + bkk;
        if (kb < K)
            vb = *reinterpret_cast<const float4*>(W + (size_t)kb * 65792 + nBase + bcq);
        else
            vb = make_float4(0.f, 0.f, 0.f, 0.f);
    };
    auto stS = [&](int s) {
#pragma unroll
        for (int j = 0; j < 4; ++j) {
            As2[s][akq + j][2 * ar]     = va[j];
            As2[s][akq + j][2 * ar + 1] = va[j];
        }
        *reinterpret_cast<float4*>(&Bs[s][bkk][bcq]) = vb;
    };

    unsigned long long acc[TM][TNH];
#pragma unroll
    for (int u = 0; u < TM; ++u)
#pragma unroll
        for (int v = 0; v < TNH; ++v) acc[u][v] = 0ull;

    loadG(0); stS(0); __syncthreads();
    for (int kt = 0; kt < NIT; ++kt) {
        if (kt + 1 < NIT) loadG((kt + 1) * BK);
        mm_tile(acc, &As2[kt & 1][0][0], &Bs[kt & 1][0][0], ty, tx);
        if (kt + 1 < NIT) { stS((kt + 1) & 1); __syncthreads(); }
    }

#pragma unroll
    for (int u = 0; u < TM; ++u) {
        size_t row = (size_t)(mBase + ty * TM + u);
        float* orow = X + row * 65792 + nBase + tx * 8;
#pragma unroll
        for (int v = 0; v < TNH; ++v)
            *reinterpret_cast<unsigned long long*>(orow + 2 * v) = acc[u][v];
    }
}

// ---------------------------------------------------------------------------
// K2: A[(n,i)][j*256+c] = sum_b l2p[n][j,b] * X1[(n,i)][b*256+c]  (B with X2)
//     2048*2 batched GEMMs M=256, K=257, N=256.  grid (2, 2, 4096)
// ---------------------------------------------------------------------------
__global__ void __launch_bounds__(256, 2)
k_gemm2(const float* __restrict__ layer2)
{
    const int tid = threadIdx.x;
    const int ty = tid >> 4, tx = tid & 15;
    const int nt = blockIdx.x, mt = blockIdx.y;
    const int mz = blockIdx.z;
    const int m = mz >> 1, w = mz & 1;
    const int n = m >> 8;

    const float* __restrict__ X = (w ? g_X2 : g_X1) + (size_t)m * 65792;
    float* __restrict__ O       = (w ? g_B : g_A) + (size_t)m * 65536;
    const float* __restrict__ L2 = layer2 + (size_t)n * 65536;

    __shared__ float As2[2][BK][2 * BM];
    __shared__ float Bs[2][BK][BN];

    const int ar  = tid >> 1;
    const int akq = (tid & 1) * 4;
    const int bkk = tid >> 5;
    const int bcq = (tid & 31) * 4;

    const int K = 257;
    const int NIT = (K + BK - 1) / BK;  // 33

    float va[4];
    float4 vb;

    auto loadG = [&](int k0) {
        int k = k0 + akq;
        int jrow = mt * BM + ar;
        if (k + 3 < 256) {
            float4 f = *reinterpret_cast<const float4*>(L2 + (size_t)jrow * 256 + k);
            va[0] = f.x; va[1] = f.y; va[2] = f.z; va[3] = f.w;
        } else {
#pragma unroll
            for (int j = 0; j < 4; ++j) {
                int kj = k + j;
                va[j] = (kj < 256) ? L2[(size_t)jrow * 256 + kj]
                                   : (kj == 256 ? 1.0f : 0.0f);
            }
        }
        int kb = k0 + bkk;
        if (kb < K)
            vb = *reinterpret_cast<const float4*>(X + (size_t)kb * 256 + nt * BN + bcq);
        else
            vb = make_float4(0.f, 0.f, 0.f, 0.f);
    };
    auto stS = [&](int s) {
#pragma unroll
        for (int j = 0; j < 4; ++j) {
            As2[s][akq + j][2 * ar]     = va[j];
            As2[s][akq + j][2 * ar + 1] = va[j];
        }
        *reinterpret_cast<float4*>(&Bs[s][bkk][bcq]) = vb;
    };

    unsigned long long acc[TM][TNH];
#pragma unroll
    for (int u = 0; u < TM; ++u)
#pragma unroll
        for (int v = 0; v < TNH; ++v) acc[u][v] = 0ull;

    loadG(0); stS(0); __syncthreads();
    for (int kt = 0; kt < NIT; ++kt) {
        if (kt + 1 < NIT) loadG((kt + 1) * BK);
        mm_tile(acc, &As2[kt & 1][0][0], &Bs[kt & 1][0][0], ty, tx);
        if (kt + 1 < NIT) { stS((kt + 1) & 1); __syncthreads(); }
    }

#pragma unroll
    for (int u = 0; u < TM; ++u) {
        size_t row = (size_t)(mt * BM + ty * TM + u);
        float* orow = O + row * 256 + nt * BN + tx * 8;
#pragma unroll
        for (int v = 0; v < TNH; ++v)
            *reinterpret_cast<unsigned long long*>(orow + 2 * v) = acc[u][v];
    }
}

// ---------------------------------------------------------------------------
// K3: per (m=(n,i), jt):  T[j,c] = sum_d (B[m][j,d]*h2[d]) * W3T[d][c]
//     out[m][j] = sum_c (A[m][j,c]*h1[c]) * T[j,c]
//     grid (2048, 2); c processed in two 128-wide halves.
// ---------------------------------------------------------------------------
__global__ void __launch_bounds__(256, 2)
k_final(const float* __restrict__ h1,
        const float* __restrict__ h2,
        float* __restrict__ out)
{
    const int tid = threadIdx.x;
    const int ty = tid >> 4, tx = tid & 15;
    const int m = blockIdx.x, jt = blockIdx.y;

    __shared__ float As2[2][BK][2 * BM];
    __shared__ float Bs[2][BK][BN];
    __shared__ float h1s[256], h2s[256];
    __shared__ float red[16][128];

    h1s[tid] = h1[(size_t)m * 256 + tid];
    h2s[tid] = h2[(size_t)m * 256 + tid];
    __syncthreads();

    const float* __restrict__ Bm = g_B + (size_t)m * 65536 + (size_t)jt * 128 * 256;
    const float* __restrict__ Am = g_A + (size_t)m * 65536 + (size_t)jt * 128 * 256;

    float outp[TM];
#pragma unroll
    for (int u = 0; u < TM; ++u) outp[u] = 0.0f;

    const int ar  = tid >> 1;
    const int akq = (tid & 1) * 4;
    const int bkk = tid >> 5;
    const int bcq = (tid & 31) * 4;

    for (int ch = 0; ch < 2; ++ch) {
        unsigned long long acc[TM][TNH];
#pragma unroll
        for (int u = 0; u < TM; ++u)
#pragma unroll
            for (int v = 0; v < TNH; ++v) acc[u][v] = 0ull;

        float va[4];
        float4 vb;

        auto loadG = [&](int k0) {
            int k = k0 + akq;
            float4 f = *reinterpret_cast<const float4*>(Bm + (size_t)ar * 256 + k);
            va[0] = f.x * h2s[k];
            va[1] = f.y * h2s[k + 1];
            va[2] = f.z * h2s[k + 2];
            va[3] = f.w * h2s[k + 3];
            vb = *reinterpret_cast<const float4*>(g_W3T + (size_t)(k0 + bkk) * 256 + ch * 128 + bcq);
        };
        auto stS = [&](int s) {
#pragma unroll
            for (int j = 0; j < 4; ++j) {
                As2[s][akq + j][2 * ar]     = va[j];
                As2[s][akq + j][2 * ar + 1] = va[j];
            }
            *reinterpret_cast<float4*>(&Bs[s][bkk][bcq]) = vb;
        };

        const int NIT = 32;  // K = 256, exact
        loadG(0); stS(0); __syncthreads();
        for (int kt = 0; kt < NIT; ++kt) {
            if (kt + 1 < NIT) loadG((kt + 1) * BK);
            mm_tile(acc, &As2[kt & 1][0][0], &Bs[kt & 1][0][0], ty, tx);
            if (kt + 1 < NIT) { stS((kt + 1) & 1); __syncthreads(); }
        }

        // epilogue: out[j] += sum_c h1[c] * A[j,c] * T[j,c]
#pragma unroll
        for (int u = 0; u < TM; ++u) {
            const float* Arow = Am + (size_t)(ty * TM + u) * 256 + ch * 128 + tx * 8;
#pragma unroll
            for (int v = 0; v < TNH; ++v) {
                float2 av = *reinterpret_cast<const float2*>(Arow + 2 * v);
                float tlo, thi;
                asm("mov.b64 {%0, %1}, %2;" : "=f"(tlo), "=f"(thi) : "l"(acc[u][v]));
                int c = ch * 128 + tx * 8 + 2 * v;
                outp[u] += av.x * h1s[c] * tlo + av.y * h1s[c + 1] * thi;
            }
        }
        // stage-buffer reuse across ch iterations is protected by the
        // prologue __syncthreads() of the next half.
    }

    __syncthreads();
#pragma unroll
    for (int u = 0; u < TM; ++u)
        red[tx][ty * TM + u] = outp[u];
    __syncthreads();

    if (tid < 128) {
        float s = 0.0f;
#pragma unroll
        for (int x = 0; x < 16; ++x) s += red[x][tid];
        out[(size_t)m * 256 + jt * 128 + tid] = s;
    }
}

// ---------------------------------------------------------------------------
extern "C" void kernel_launch(void* const* d_in, const int* in_sizes, int n_in,
                              void* d_out, int out_size)
{
    const float* layer1 = (const float*)d_in[0];
    const float* layer2 = (const float*)d_in[1];
    const float* h1     = (const float*)d_in[2];
    const float* h2     = (const float*)d_in[3];
    const float* W1     = (const float*)d_in[4];
    const float* W2     = (const float*)d_in[5];
    const float* W3     = (const float*)d_in[6];
    float* out = (float*)d_out;

    k_transpose<<<dim3(8, 8), dim3(32, 32)>>>(W3);
    k_gemm1<<<dim3(514, 16, 2), 256>>>(layer1, W1, W2);
    k_gemm2<<<dim3(2, 2, 4096), 256>>>(layer2);
    k_final<<<dim3(2048, 2), 256>>>(h1, h2, out);
}

// round 2
// speedup vs baseline: 1.0511x; 1.0511x over previous
#include <cuda_runtime.h>

// ---------------------------------------------------------------------------
// Triaffine:  out[n,i,j] = sum_{c,d} (h1[nic] * A[nijc]) * W3[c,d] * (h2[nid] * B[nijd])
//   A[nijc] = sum_{a,b} l1[nia] W1[abc] l2[njb]   (l1/l2 = [layer, ones])
//   B likewise with W2.
// Staged as 3 GEMM passes through __device__ scratch + a final fused
// GEMM+reduce. All fp32, inner loops use packed fma.rn.f32x2 (2x FFMA rate).
// ---------------------------------------------------------------------------

#define BM 128
#define BN 128
#define BK 8
#define TM 8
#define TNH 4   // TN/2 packed pairs (TN = 8)

// Scratch (module-load allocated; no runtime alloc)
__device__ __align__(16) float g_X1[2048ull * 257 * 256];   // 539 MB
__device__ __align__(16) float g_X2[2048ull * 257 * 256];   // 539 MB
__device__ __align__(16) float g_A [2048ull * 256 * 256];   // 537 MB
__device__ __align__(16) float g_B [2048ull * 256 * 256];   // 537 MB
__device__ __align__(16) float g_W3T[256 * 256];

// ---------------------------------------------------------------------------
// Inner 128x128 micro-tile step over BK k-slices.
// As2: [BK][2*BM] with every A value duplicated (so LDS.64 -> packed (a,a)).
// Bs : [BK][BN].
// ---------------------------------------------------------------------------
__device__ __forceinline__ void mm_tile(unsigned long long acc[TM][TNH],
                                        const float* __restrict__ As2,
                                        const float* __restrict__ Bs,
                                        int ty, int tx)
{
#pragma unroll
    for (int kk = 0; kk < BK; ++kk) {
        unsigned long long a[TM], b[TNH];
        const float* ar = As2 + kk * (2 * BM) + 2 * (ty * TM);
        const float* br = Bs + kk * BN + tx * 8;
#pragma unroll
        for (int u = 0; u < TM; ++u)
            a[u] = *reinterpret_cast<const unsigned long long*>(ar + 2 * u);
#pragma unroll
        for (int v = 0; v < TNH; ++v)
            b[v] = *reinterpret_cast<const unsigned long long*>(br + 2 * v);
#pragma unroll
        for (int u = 0; u < TM; ++u)
#pragma unroll
            for (int v = 0; v < TNH; ++v)
                asm("fma.rn.f32x2 %0, %1, %2, %0;"
                    : "+l"(acc[u][v]) : "l"(a[u]), "l"(b[v]));
    }
}

// ---------------------------------------------------------------------------
// K0: transpose W3 -> g_W3T  (so the final GEMM reads it row-major)
// ---------------------------------------------------------------------------
__global__ void k_transpose(const float* __restrict__ W3)
{
    __shared__ float t[32][33];
    int bx = blockIdx.x * 32, by = blockIdx.y * 32;
    t[threadIdx.y][threadIdx.x] = W3[(size_t)(by + threadIdx.y) * 256 + bx + threadIdx.x];
    __syncthreads();
    g_W3T[(size_t)(bx + threadIdx.y) * 256 + by + threadIdx.x] = t[threadIdx.x][threadIdx.y];
}

// ---------------------------------------------------------------------------
// K1: X{1,2}[(n,i)][b*256+c] = sum_a l1p[(n,i),a] * W{1,2}[a][b*256+c]
//     GEMM M=2048, K=257, N=65792.  grid (514, 16, 2)
// ---------------------------------------------------------------------------
__global__ void __launch_bounds__(256, 2)
k_gemm1(const float* __restrict__ layer1,
        const float* __restrict__ W1,
        const float* __restrict__ W2)
{
    const int tid = threadIdx.x;
    const int ty = tid >> 4, tx = tid & 15;
    const int nBase = blockIdx.x * BN;
    const int mBase = blockIdx.y * BM;
    const float* __restrict__ W = blockIdx.z ? W2 : W1;
    float* __restrict__ X = blockIdx.z ? g_X2 : g_X1;

    __shared__ float As2[2][BK][2 * BM];
    __shared__ float Bs[2][BK][BN];

    const int ar  = tid >> 1;           // A row within tile (0..127)
    const int akq = (tid & 1) * 4;      // A k-quad offset
    const int bkk = tid >> 5;           // B k row (0..7)
    const int bcq = (tid & 31) * 4;     // B col quad

    const int K = 257;
    const int NIT = (K + BK - 1) / BK;  // 33

    float va[4];
    float4 vb;

    auto loadG = [&](int k0) {
        int k = k0 + akq;
        int mrow = mBase + ar;
        if (k + 3 < 256) {
            float4 f = *reinterpret_cast<const float4*>(layer1 + (size_t)mrow * 256 + k);
            va[0] = f.x; va[1] = f.y; va[2] = f.z; va[3] = f.w;
        } else {
#pragma unroll
            for (int j = 0; j < 4; ++j) {
                int kj = k + j;
                va[j] = (kj < 256) ? layer1[(size_t)mrow * 256 + kj]
                                   : (kj == 256 ? 1.0f : 0.0f);
            }
        }
        int kb = k0 + bkk;
        if (kb < K)
            vb = *reinterpret_cast<const float4*>(W + (size_t)kb * 65792 + nBase + bcq);
        else
            vb = make_float4(0.f, 0.f, 0.f, 0.f);
    };
    auto stS = [&](int s) {
#pragma unroll
        for (int j = 0; j < 4; ++j) {
            As2[s][akq + j][2 * ar]     = va[j];
            As2[s][akq + j][2 * ar + 1] = va[j];
        }
        *reinterpret_cast<float4*>(&Bs[s][bkk][bcq]) = vb;
    };

    unsigned long long acc[TM][TNH];
#pragma unroll
    for (int u = 0; u < TM; ++u)
#pragma unroll
        for (int v = 0; v < TNH; ++v) acc[u][v] = 0ull;

    loadG(0); stS(0); __syncthreads();
    for (int kt = 0; kt < NIT; ++kt) {
        if (kt + 1 < NIT) loadG((kt + 1) * BK);
        mm_tile(acc, &As2[kt & 1][0][0], &Bs[kt & 1][0][0], ty, tx);
        if (kt + 1 < NIT) { stS((kt + 1) & 1); __syncthreads(); }
    }

#pragma unroll
    for (int u = 0; u < TM; ++u) {
        size_t row = (size_t)(mBase + ty * TM + u);
        float* orow = X + row * 65792 + nBase + tx * 8;
#pragma unroll
        for (int v = 0; v < TNH; ++v)
            *reinterpret_cast<unsigned long long*>(orow + 2 * v) = acc[u][v];
    }
}

// ---------------------------------------------------------------------------
// K2: A[(n,i)][j*256+c] = sum_b l2p[n][j,b] * X1[(n,i)][b*256+c]  (B with X2)
//     2048*2 batched GEMMs M=256, K=257, N=256.  grid (2, 2, 4096)
// ---------------------------------------------------------------------------
__global__ void __launch_bounds__(256, 2)
k_gemm2(const float* __restrict__ layer2)
{
    const int tid = threadIdx.x;
    const int ty = tid >> 4, tx = tid & 15;
    const int nt = blockIdx.x, mt = blockIdx.y;
    const int mz = blockIdx.z;
    const int m = mz >> 1, w = mz & 1;
    const int n = m >> 8;

    const float* __restrict__ X = (w ? g_X2 : g_X1) + (size_t)m * 65792;
    float* __restrict__ O       = (w ? g_B : g_A) + (size_t)m * 65536;
    const float* __restrict__ L2 = layer2 + (size_t)n * 65536;

    __shared__ float As2[2][BK][2 * BM];
    __shared__ float Bs[2][BK][BN];

    const int ar  = tid >> 1;
    const int akq = (tid & 1) * 4;
    const int bkk = tid >> 5;
    const int bcq = (tid & 31) * 4;

    const int K = 257;
    const int NIT = (K + BK - 1) / BK;  // 33

    float va[4];
    float4 vb;

    auto loadG = [&](int k0) {
        int k = k0 + akq;
        int jrow = mt * BM + ar;
        if (k + 3 < 256) {
            float4 f = *reinterpret_cast<const float4*>(L2 + (size_t)jrow * 256 + k);
            va[0] = f.x; va[1] = f.y; va[2] = f.z; va[3] = f.w;
        } else {
#pragma unroll
            for (int j = 0; j < 4; ++j) {
                int kj = k + j;
                va[j] = (kj < 256) ? L2[(size_t)jrow * 256 + kj]
                                   : (kj == 256 ? 1.0f : 0.0f);
            }
        }
        int kb = k0 + bkk;
        if (kb < K)
            vb = *reinterpret_cast<const float4*>(X + (size_t)kb * 256 + nt * BN + bcq);
        else
            vb = make_float4(0.f, 0.f, 0.f, 0.f);
    };
    auto stS = [&](int s) {
#pragma unroll
        for (int j = 0; j < 4; ++j) {
            As2[s][akq + j][2 * ar]     = va[j];
            As2[s][akq + j][2 * ar + 1] = va[j];
        }
        *reinterpret_cast<float4*>(&Bs[s][bkk][bcq]) = vb;
    };

    unsigned long long acc[TM][TNH];
#pragma unroll
    for (int u = 0; u < TM; ++u)
#pragma unroll
        for (int v = 0; v < TNH; ++v) acc[u][v] = 0ull;

    loadG(0); stS(0); __syncthreads();
    for (int kt = 0; kt < NIT; ++kt) {
        if (kt + 1 < NIT) loadG((kt + 1) * BK);
        mm_tile(acc, &As2[kt & 1][0][0], &Bs[kt & 1][0][0], ty, tx);
        if (kt + 1 < NIT) { stS((kt + 1) & 1); __syncthreads(); }
    }

#pragma unroll
    for (int u = 0; u < TM; ++u) {
        size_t row = (size_t)(mt * BM + ty * TM + u);
        float* orow = O + row * 256 + nt * BN + tx * 8;
#pragma unroll
        for (int v = 0; v < TNH; ++v)
            *reinterpret_cast<unsigned long long*>(orow + 2 * v) = acc[u][v];
    }
}

// ---------------------------------------------------------------------------
// K3: per (m=(n,i), jt):  T[j,c] = sum_d (B[m][j,d]*h2[d]) * W3T[d][c]
//     out[m][j] = sum_c (A[m][j,c]*h1[c]) * T[j,c]
//     grid (2048, 2); c processed in two 128-wide halves.
// ---------------------------------------------------------------------------
__global__ void __launch_bounds__(256, 2)
k_final(const float* __restrict__ h1,
        const float* __restrict__ h2,
        float* __restrict__ out)
{
    const int tid = threadIdx.x;
    const int ty = tid >> 4, tx = tid & 15;
    const int m = blockIdx.x, jt = blockIdx.y;

    __shared__ float As2[2][BK][2 * BM];
    __shared__ float Bs[2][BK][BN];
    __shared__ float h1s[256], h2s[256];
    __shared__ float red[16][128];

    h1s[tid] = h1[(size_t)m * 256 + tid];
    h2s[tid] = h2[(size_t)m * 256 + tid];
    __syncthreads();

    const float* __restrict__ Bm = g_B + (size_t)m * 65536 + (size_t)jt * 128 * 256;
    const float* __restrict__ Am = g_A + (size_t)m * 65536 + (size_t)jt * 128 * 256;

    float outp[TM];
#pragma unroll
    for (int u = 0; u < TM; ++u) outp[u] = 0.0f;

    const int ar  = tid >> 1;
    const int akq = (tid & 1) * 4;
    const int bkk = tid >> 5;
    const int bcq = (tid & 31) * 4;

    for (int ch = 0; ch < 2; ++ch) {
        unsigned long long acc[TM][TNH];
#pragma unroll
        for (int u = 0; u < TM; ++u)
#pragma unroll
            for (int v = 0; v < TNH; ++v) acc[u][v] = 0ull;

        float va[4];
        float4 vb;

        auto loadG = [&](int k0) {
            int k = k0 + akq;
            float4 f = *reinterpret_cast<const float4*>(Bm + (size_t)ar * 256 + k);
            va[0] = f.x * h2s[k];
            va[1] = f.y * h2s[k + 1];
            va[2] = f.z * h2s[k + 2];
            va[3] = f.w * h2s[k + 3];
            vb = *reinterpret_cast<const float4*>(g_W3T + (size_t)(k0 + bkk) * 256 + ch * 128 + bcq);
        };
        auto stS = [&](int s) {
#pragma unroll
            for (int j = 0; j < 4; ++j) {
                As2[s][akq + j][2 * ar]     = va[j];
                As2[s][akq + j][2 * ar + 1] = va[j];
            }
            *reinterpret_cast<float4*>(&Bs[s][bkk][bcq]) = vb;
        };

        const int NIT = 32;  // K = 256, exact
        loadG(0); stS(0); __syncthreads();
        for (int kt = 0; kt < NIT; ++kt) {
            if (kt + 1 < NIT) loadG((kt + 1) * BK);
            mm_tile(acc, &As2[kt & 1][0][0], &Bs[kt & 1][0][0], ty, tx);
            if (kt + 1 < NIT) { stS((kt + 1) & 1); __syncthreads(); }
        }

        // epilogue: out[j] += sum_c h1[c] * A[j,c] * T[j,c]
#pragma unroll
        for (int u = 0; u < TM; ++u) {
            const float* Arow = Am + (size_t)(ty * TM + u) * 256 + ch * 128 + tx * 8;
#pragma unroll
            for (int v = 0; v < TNH; ++v) {
                float2 av = *reinterpret_cast<const float2*>(Arow + 2 * v);
                float tlo, thi;
                asm("mov.b64 {%0, %1}, %2;" : "=f"(tlo), "=f"(thi) : "l"(acc[u][v]));
                int c = ch * 128 + tx * 8 + 2 * v;
                outp[u] += av.x * h1s[c] * tlo + av.y * h1s[c + 1] * thi;
            }
        }
        // stage-buffer reuse across ch iterations is protected by the
        // prologue __syncthreads() of the next half.
    }

    __syncthreads();
#pragma unroll
    for (int u = 0; u < TM; ++u)
        red[tx][ty * TM + u] = outp[u];
    __syncthreads();

    if (tid < 128) {
        float s = 0.0f;
#pragma unroll
        for (int x = 0; x < 16; ++x) s += red[x][tid];
        out[(size_t)m * 256 + jt * 128 + tid] = s;
    }
}

// ---------------------------------------------------------------------------
extern "C" void kernel_launch(void* const* d_in, const int* in_sizes, int n_in,
                              void* d_out, int out_size)
{
    const float* layer1 = (const float*)d_in[0];
    const float* layer2 = (const float*)d_in[1];
    const float* h1     = (const float*)d_in[2];
    const float* h2     = (const float*)d_in[3];
    const float* W1     = (const float*)d_in[4];
    const float* W2     = (const float*)d_in[5];
    const float* W3     = (const float*)d_in[6];
    float* out = (float*)d_out;

    k_transpose<<<dim3(8, 8), dim3(32, 32)>>>(W3);
    k_gemm1<<<dim3(514, 16, 2), 256>>>(layer1, W1, W2);
    k_gemm2<<<dim3(2, 2, 4096), 256>>>(layer2);
    k_final<<<dim3(2048, 2), 256>>>(h1, h2, out);
}

// round 3
// speedup vs baseline: 1.0536x; 1.0023x over previous
#include <cuda_runtime.h>

// ---------------------------------------------------------------------------
// Triaffine:  out[n,i,j] = sum_{c,d} (h1[nic] * A[nijc]) * W3[c,d] * (h2[nid] * B[nijd])
//   A[nijc] = sum_{a,b} l1[nia] W1[abc] l2[njb]   (l1/l2 = [layer, ones])
//   B likewise with W2.
// Staged as 3 GEMM passes through __device__ scratch + a final fused
// GEMM+reduce. All fp32, inner loops use packed fma.rn.f32x2 (2x FFMA rate).
// ---------------------------------------------------------------------------

#define BM 128
#define BN 128
#define BK 8
#define TM 8
#define TNH 4   // TN/2 packed pairs (TN = 8)

// Scratch (module-load allocated; no runtime alloc)
__device__ __align__(16) float g_X1[2048ull * 257 * 256];   // 539 MB
__device__ __align__(16) float g_X2[2048ull * 257 * 256];   // 539 MB
__device__ __align__(16) float g_A [2048ull * 256 * 256];   // 537 MB
__device__ __align__(16) float g_B [2048ull * 256 * 256];   // 537 MB
__device__ __align__(16) float g_W3T[256 * 256];

// ---------------------------------------------------------------------------
// Inner 128x128 micro-tile step over BK k-slices.
// As2: [BK][2*BM] with every A value duplicated (so LDS.64 -> packed (a,a)).
// Bs : [BK][BN].
// ---------------------------------------------------------------------------
__device__ __forceinline__ void mm_tile(unsigned long long acc[TM][TNH],
                                        const float* __restrict__ As2,
                                        const float* __restrict__ Bs,
                                        int ty, int tx)
{
#pragma unroll
    for (int kk = 0; kk < BK; ++kk) {
        unsigned long long a[TM], b[TNH];
        const float* ar = As2 + kk * (2 * BM) + 2 * (ty * TM);
        const float* br = Bs + kk * BN + tx * 8;
#pragma unroll
        for (int u = 0; u < TM; ++u)
            a[u] = *reinterpret_cast<const unsigned long long*>(ar + 2 * u);
#pragma unroll
        for (int v = 0; v < TNH; ++v)
            b[v] = *reinterpret_cast<const unsigned long long*>(br + 2 * v);
#pragma unroll
        for (int u = 0; u < TM; ++u)
#pragma unroll
            for (int v = 0; v < TNH; ++v)
                asm("fma.rn.f32x2 %0, %1, %2, %0;"
                    : "+l"(acc[u][v]) : "l"(a[u]), "l"(b[v]));
    }
}

// ---------------------------------------------------------------------------
// K0: transpose W3 -> g_W3T  (so the final GEMM reads it row-major)
// ---------------------------------------------------------------------------
__global__ void k_transpose(const float* __restrict__ W3)
{
    __shared__ float t[32][33];
    int bx = blockIdx.x * 32, by = blockIdx.y * 32;
    t[threadIdx.y][threadIdx.x] = W3[(size_t)(by + threadIdx.y) * 256 + bx + threadIdx.x];
    __syncthreads();
    g_W3T[(size_t)(bx + threadIdx.y) * 256 + by + threadIdx.x] = t[threadIdx.x][threadIdx.y];
}

// ---------------------------------------------------------------------------
// K1: X{1,2}[(n,i)][b*256+c] = sum_a l1p[(n,i),a] * W{1,2}[a][b*256+c]
//     GEMM M=2048, K=257, N=65792.  grid (514, 16, 2)
// ---------------------------------------------------------------------------
__global__ void __launch_bounds__(256, 2)
k_gemm1(const float* __restrict__ layer1,
        const float* __restrict__ W1,
        const float* __restrict__ W2)
{
    const int tid = threadIdx.x;
    const int ty = tid >> 4, tx = tid & 15;
    const int nBase = blockIdx.x * BN;
    const int mBase = blockIdx.y * BM;
    const float* __restrict__ W = blockIdx.z ? W2 : W1;
    float* __restrict__ X = blockIdx.z ? g_X2 : g_X1;

    __shared__ float As2[2][BK][2 * BM];
    __shared__ float Bs[2][BK][BN];

    const int ar  = tid >> 1;           // A row within tile (0..127)
    const int akq = (tid & 1) * 4;      // A k-quad offset
    const int bkk = tid >> 5;           // B k row (0..7)
    const int bcq = (tid & 31) * 4;     // B col quad

    const int K = 257;
    const int NIT = (K + BK - 1) / BK;  // 33

    float va[4];
    float4 vb;

    auto loadG = [&](int k0) {
        int k = k0 + akq;
        int mrow = mBase + ar;
        if (k + 3 < 256) {
            float4 f = *reinterpret_cast<const float4*>(layer1 + (size_t)mrow * 256 + k);
            va[0] = f.x; va[1] = f.y; va[2] = f.z; va[3] = f.w;
        } else {
#pragma unroll
            for (int j = 0; j < 4; ++j) {
                int kj = k + j;
                va[j] = (kj < 256) ? layer1[(size_t)mrow * 256 + kj]
                                   : (kj == 256 ? 1.0f : 0.0f);
            }
        }
        int kb = k0 + bkk;
        if (kb < K)
            vb = *reinterpret_cast<const float4*>(W + (size_t)kb * 65792 + nBase + bcq);
        else
            vb = make_float4(0.f, 0.f, 0.f, 0.f);
    };
    auto stS = [&](int s) {
#pragma unroll
        for (int j = 0; j < 4; ++j) {
            As2[s][akq + j][2 * ar]     = va[j];
            As2[s][akq + j][2 * ar + 1] = va[j];
        }
        *reinterpret_cast<float4*>(&Bs[s][bkk][bcq]) = vb;
    };

    unsigned long long acc[TM][TNH];
#pragma unroll
    for (int u = 0; u < TM; ++u)
#pragma unroll
        for (int v = 0; v < TNH; ++v) acc[u][v] = 0ull;

    loadG(0); stS(0); __syncthreads();
    for (int kt = 0; kt < NIT; ++kt) {
        if (kt + 1 < NIT) loadG((kt + 1) * BK);
        mm_tile(acc, &As2[kt & 1][0][0], &Bs[kt & 1][0][0], ty, tx);
        if (kt + 1 < NIT) { stS((kt + 1) & 1); __syncthreads(); }
    }

#pragma unroll
    for (int u = 0; u < TM; ++u) {
        size_t row = (size_t)(mBase + ty * TM + u);
        float* orow = X + row * 65792 + nBase + tx * 8;
#pragma unroll
        for (int v = 0; v < TNH; ++v)
            *reinterpret_cast<unsigned long long*>(orow + 2 * v) = acc[u][v];
    }
}

// ---------------------------------------------------------------------------
// K2: A[(n,i)][j*256+c] = sum_b l2p[n][j,b] * X1[(n,i)][b*256+c]  (B with X2)
//     2048*2 batched GEMMs M=256, K=257, N=256.  grid (2, 2, 4096)
// ---------------------------------------------------------------------------
__global__ void __launch_bounds__(256, 2)
k_gemm2(const float* __restrict__ layer2)
{
    const int tid = threadIdx.x;
    const int ty = tid >> 4, tx = tid & 15;
    const int nt = blockIdx.x, mt = blockIdx.y;
    const int mz = blockIdx.z;
    const int m = mz >> 1, w = mz & 1;
    const int n = m >> 8;

    const float* __restrict__ X = (w ? g_X2 : g_X1) + (size_t)m * 65792;
    float* __restrict__ O       = (w ? g_B : g_A) + (size_t)m * 65536;
    const float* __restrict__ L2 = layer2 + (size_t)n * 65536;

    __shared__ float As2[2][BK][2 * BM];
    __shared__ float Bs[2][BK][BN];

    const int ar  = tid >> 1;
    const int akq = (tid & 1) * 4;
    const int bkk = tid >> 5;
    const int bcq = (tid & 31) * 4;

    const int K = 257;
    const int NIT = (K + BK - 1) / BK;  // 33

    float va[4];
    float4 vb;

    auto loadG = [&](int k0) {
        int k = k0 + akq;
        int jrow = mt * BM + ar;
        if (k + 3 < 256) {
            float4 f = *reinterpret_cast<const float4*>(L2 + (size_t)jrow * 256 + k);
            va[0] = f.x; va[1] = f.y; va[2] = f.z; va[3] = f.w;
        } else {
#pragma unroll
            for (int j = 0; j < 4; ++j) {
                int kj = k + j;
                va[j] = (kj < 256) ? L2[(size_t)jrow * 256 + kj]
                                   : (kj == 256 ? 1.0f : 0.0f);
            }
        }
        int kb = k0 + bkk;
        if (kb < K)
            vb = *reinterpret_cast<const float4*>(X + (size_t)kb * 256 + nt * BN + bcq);
        else
            vb = make_float4(0.f, 0.f, 0.f, 0.f);
    };
    auto stS = [&](int s) {
#pragma unroll
        for (int j = 0; j < 4; ++j) {
            As2[s][akq + j][2 * ar]     = va[j];
            As2[s][akq + j][2 * ar + 1] = va[j];
        }
        *reinterpret_cast<float4*>(&Bs[s][bkk][bcq]) = vb;
    };

    unsigned long long acc[TM][TNH];
#pragma unroll
    for (int u = 0; u < TM; ++u)
#pragma unroll
        for (int v = 0; v < TNH; ++v) acc[u][v] = 0ull;

    loadG(0); stS(0); __syncthreads();
    for (int kt = 0; kt < NIT; ++kt) {
        if (kt + 1 < NIT) loadG((kt + 1) * BK);
        mm_tile(acc, &As2[kt & 1][0][0], &Bs[kt & 1][0][0], ty, tx);
        if (kt + 1 < NIT) { stS((kt + 1) & 1); __syncthreads(); }
    }

#pragma unroll
    for (int u = 0; u < TM; ++u) {
        size_t row = (size_t)(mt * BM + ty * TM + u);
        float* orow = O + row * 256 + nt * BN + tx * 8;
#pragma unroll
        for (int v = 0; v < TNH; ++v)
            *reinterpret_cast<unsigned long long*>(orow + 2 * v) = acc[u][v];
    }
}

// ---------------------------------------------------------------------------
// K3: per (m=(n,i), jt):  T[j,c] = sum_d (B[m][j,d]*h2[d]) * W3T[d][c]
//     out[m][j] = sum_c (A[m][j,c]*h1[c]) * T[j,c]
//     grid (2048, 2); c processed in two 128-wide halves.
// ---------------------------------------------------------------------------
__global__ void __launch_bounds__(256, 2)
k_final(const float* __restrict__ h1,
        const float* __restrict__ h2,
        float* __restrict__ out)
{
    const int tid = threadIdx.x;
    const int ty = tid >> 4, tx = tid & 15;
    const int m = blockIdx.x, jt = blockIdx.y;

    __shared__ float As2[2][BK][2 * BM];
    __shared__ float Bs[2][BK][BN];
    __shared__ float h1s[256], h2s[256];
    __shared__ float red[16][128];

    h1s[tid] = h1[(size_t)m * 256 + tid];
    h2s[tid] = h2[(size_t)m * 256 + tid];
    __syncthreads();

    const float* __restrict__ Bm = g_B + (size_t)m * 65536 + (size_t)jt * 128 * 256;
    const float* __restrict__ Am = g_A + (size_t)m * 65536 + (size_t)jt * 128 * 256;

    float outp[TM];
#pragma unroll
    for (int u = 0; u < TM; ++u) outp[u] = 0.0f;

    const int ar  = tid >> 1;
    const int akq = (tid & 1) * 4;
    const int bkk = tid >> 5;
    const int bcq = (tid & 31) * 4;

    for (int ch = 0; ch < 2; ++ch) {
        unsigned long long acc[TM][TNH];
#pragma unroll
        for (int u = 0; u < TM; ++u)
#pragma unroll
            for (int v = 0; v < TNH; ++v) acc[u][v] = 0ull;

        float va[4];
        float4 vb;

        auto loadG = [&](int k0) {
            int k = k0 + akq;
            float4 f = *reinterpret_cast<const float4*>(Bm + (size_t)ar * 256 + k);
            va[0] = f.x * h2s[k];
            va[1] = f.y * h2s[k + 1];
            va[2] = f.z * h2s[k + 2];
            va[3] = f.w * h2s[k + 3];
            vb = *reinterpret_cast<const float4*>(g_W3T + (size_t)(k0 + bkk) * 256 + ch * 128 + bcq);
        };
        auto stS = [&](int s) {
#pragma unroll
            for (int j = 0; j < 4; ++j) {
                As2[s][akq + j][2 * ar]     = va[j];
                As2[s][akq + j][2 * ar + 1] = va[j];
            }
            *reinterpret_cast<float4*>(&Bs[s][bkk][bcq]) = vb;
        };

        const int NIT = 32;  // K = 256, exact
        loadG(0); stS(0); __syncthreads();
        for (int kt = 0; kt < NIT; ++kt) {
            if (kt + 1 < NIT) loadG((kt + 1) * BK);
            mm_tile(acc, &As2[kt & 1][0][0], &Bs[kt & 1][0][0], ty, tx);
            if (kt + 1 < NIT) { stS((kt + 1) & 1); __syncthreads(); }
        }

        // epilogue: out[j] += sum_c h1[c] * A[j,c] * T[j,c]
#pragma unroll
        for (int u = 0; u < TM; ++u) {
            const float* Arow = Am + (size_t)(ty * TM + u) * 256 + ch * 128 + tx * 8;
#pragma unroll
            for (int v = 0; v < TNH; ++v) {
                float2 av = *reinterpret_cast<const float2*>(Arow + 2 * v);
                float tlo, thi;
                asm("mov.b64 {%0, %1}, %2;" : "=f"(tlo), "=f"(thi) : "l"(acc[u][v]));
                int c = ch * 128 + tx * 8 + 2 * v;
                outp[u] += av.x * h1s[c] * tlo + av.y * h1s[c + 1] * thi;
            }
        }
        // stage-buffer reuse across ch iterations is protected by the
        // prologue __syncthreads() of the next half.
    }

    __syncthreads();
#pragma unroll
    for (int u = 0; u < TM; ++u)
        red[tx][ty * TM + u] = outp[u];
    __syncthreads();

    if (tid < 128) {
        float s = 0.0f;
#pragma unroll
        for (int x = 0; x < 16; ++x) s += red[x][tid];
        out[(size_t)m * 256 + jt * 128 + tid] = s;
    }
}

// ---------------------------------------------------------------------------
extern "C" void kernel_launch(void* const* d_in, const int* in_sizes, int n_in,
                              void* d_out, int out_size)
{
    const float* layer1 = (const float*)d_in[0];
    const float* layer2 = (const float*)d_in[1];
    const float* h1     = (const float*)d_in[2];
    const float* h2     = (const float*)d_in[3];
    const float* W1     = (const float*)d_in[4];
    const float* W2     = (const float*)d_in[5];
    const float* W3     = (const float*)d_in[6];
    float* out = (float*)d_out;

    k_transpose<<<dim3(8, 8), dim3(32, 32)>>>(W3);
    k_gemm1<<<dim3(514, 16, 2), 256>>>(layer1, W1, W2);
    k_gemm2<<<dim3(2, 2, 4096), 256>>>(layer2);
    k_final<<<dim3(2048, 2), 256>>>(h1, h2, out);
}

// round 4
// speedup vs baseline: 1.4186x; 1.3465x over previous
#include <cuda_runtime.h>

// ---------------------------------------------------------------------------
// Triaffine:  out[n,i,j] = sum_{c,d} (h1[nic] * A[nijc]) * W3[c,d] * (h2[nid] * B[nijd])
//   A[nijc] = sum_{a,b} l1[nia] W1[abc] l2[njb]   (l1/l2 = [layer, ones])
//   B likewise with W2.
//
// v2: exact K=256 GEMMs (ones-column folded into an epilogue bias add),
// m-pair f32x2 accumulators (A pairs come free from LDS.128; B duplicated
// into (b,b) pairs with register MOVs instead of duplicated smem), BK=16.
// Crossbar traffic per 64 MACs/thread: 64B (was 96B) -> fma-pipe parity.
// ---------------------------------------------------------------------------

#define BM 128
#define BN 128
#define BK 16
#define NIT 16   // K = 256 exactly

// Scratch (module-load allocated; no runtime alloc)
__device__ __align__(16) float g_X1[2048ull * 257 * 256];
__device__ __align__(16) float g_X2[2048ull * 257 * 256];
__device__ __align__(16) float g_A [2048ull * 256 * 256];
__device__ __align__(16) float g_B [2048ull * 256 * 256];
__device__ __align__(16) float g_W3T[256 * 256];

// ---------------------------------------------------------------------------
// Inner 128x128 micro-step over BK k-slices.
// As: [BK][BM] plain.  Bs: [BK][BN] plain.
// acc[u][v] = packed pair (C[m0][n], C[m0+1][n]) with m0 = ty*8 + 2u,
// n = tx*8 + v.  A pairs are register-aliased halves of LDS.128 loads.
// ---------------------------------------------------------------------------
__device__ __forceinline__ void mm_tile16(unsigned long long acc[4][8],
                                          const float* __restrict__ As,
                                          const float* __restrict__ Bs,
                                          int ty, int tx)
{
#pragma unroll
    for (int kk = 0; kk < BK; ++kk) {
        ulonglong2 A0 = *reinterpret_cast<const ulonglong2*>(As + kk * BM + ty * 8);
        ulonglong2 A1 = *reinterpret_cast<const ulonglong2*>(As + kk * BM + ty * 8 + 4);
        unsigned long long ap[4];
        ap[0] = A0.x; ap[1] = A0.y; ap[2] = A1.x; ap[3] = A1.y;
        float4 b0 = *reinterpret_cast<const float4*>(Bs + kk * BN + tx * 8);
        float4 b1 = *reinterpret_cast<const float4*>(Bs + kk * BN + tx * 8 + 4);
        float bb[8];
        bb[0] = b0.x; bb[1] = b0.y; bb[2] = b0.z; bb[3] = b0.w;
        bb[4] = b1.x; bb[5] = b1.y; bb[6] = b1.z; bb[7] = b1.w;
#pragma unroll
        for (int v = 0; v < 8; ++v) {
            unsigned long long bp;
            asm("mov.b64 %0, {%1, %1};" : "=l"(bp) : "f"(bb[v]));
#pragma unroll
            for (int u = 0; u < 4; ++u)
                asm("fma.rn.f32x2 %0, %1, %2, %0;"
                    : "+l"(acc[u][v]) : "l"(ap[u]), "l"(bp));
        }
    }
}

__device__ __forceinline__ void unpack_acc(float c[8][8],
                                           const unsigned long long acc[4][8])
{
#pragma unroll
    for (int u = 0; u < 4; ++u)
#pragma unroll
        for (int v = 0; v < 8; ++v)
            asm("mov.b64 {%0, %1}, %2;"
                : "=f"(c[2 * u][v]), "=f"(c[2 * u + 1][v]) : "l"(acc[u][v]));
}

// ---------------------------------------------------------------------------
// K0: transpose W3 -> g_W3T
// ---------------------------------------------------------------------------
__global__ void k_transpose(const float* __restrict__ W3)
{
    __shared__ float t[32][33];
    int bx = blockIdx.x * 32, by = blockIdx.y * 32;
    t[threadIdx.y][threadIdx.x] = W3[(size_t)(by + threadIdx.y) * 256 + bx + threadIdx.x];
    __syncthreads();
    g_W3T[(size_t)(bx + threadIdx.y) * 256 + by + threadIdx.x] = t[threadIdx.x][threadIdx.y];
}

// ---------------------------------------------------------------------------
// K1: X{1,2}[m][bc] = sum_{a<256} l1[m,a] W{1,2}[a][bc] + W{1,2}[256][bc]
//     GEMM M=2048, K=256, N=65792 + bias.  grid (514, 16, 2)
// ---------------------------------------------------------------------------
__global__ void __launch_bounds__(256, 2)
k_gemm1(const float* __restrict__ layer1,
        const float* __restrict__ W1,
        const float* __restrict__ W2)
{
    const int tid = threadIdx.x;
    const int ty = tid >> 4, tx = tid & 15;
    const int nBase = blockIdx.x * BN;
    const int mBase = blockIdx.y * BM;
    const float* __restrict__ W = blockIdx.z ? W2 : W1;
    float* __restrict__ X = blockIdx.z ? g_X2 : g_X1;

    __shared__ float As[2][BK][BM];
    __shared__ float Bs[2][BK][BN];

    const int ar  = tid >> 1;           // A row within tile (0..127)
    const int kh  = (tid & 1) * 8;      // A k offset {0, 8}
    const int bkk = tid >> 4;           // B k row (0..15)
    const int bcq = (tid & 15) * 8;     // B col offset

    float va[8];
    float4 vb0, vb1;

    auto loadG = [&](int k0) {
        const float* ap = layer1 + (size_t)(mBase + ar) * 256 + k0 + kh;
        *reinterpret_cast<float4*>(va)     = *reinterpret_cast<const float4*>(ap);
        *reinterpret_cast<float4*>(va + 4) = *reinterpret_cast<const float4*>(ap + 4);
        const float* bp = W + (size_t)(k0 + bkk) * 65792 + nBase + bcq;
        vb0 = *reinterpret_cast<const float4*>(bp);
        vb1 = *reinterpret_cast<const float4*>(bp + 4);
    };
    auto stS = [&](int s) {
#pragma unroll
        for (int i = 0; i < 8; ++i) As[s][kh + i][ar] = va[i];
        *reinterpret_cast<float4*>(&Bs[s][bkk][bcq])     = vb0;
        *reinterpret_cast<float4*>(&Bs[s][bkk][bcq + 4]) = vb1;
    };

    unsigned long long acc[4][8];
#pragma unroll
    for (int u = 0; u < 4; ++u)
#pragma unroll
        for (int v = 0; v < 8; ++v) acc[u][v] = 0ull;

    loadG(0); stS(0); __syncthreads();
    for (int kt = 0; kt < NIT; ++kt) {
        if (kt + 1 < NIT) loadG((kt + 1) * BK);
        mm_tile16(acc, &As[kt & 1][0][0], &Bs[kt & 1][0][0], ty, tx);
        if (kt + 1 < NIT) { stS((kt + 1) & 1); __syncthreads(); }
    }

    float c[8][8];
    unpack_acc(c, acc);

    // bias: ones-column contribution = W[256][col]
    float bias[8];
    const float* brow = W + 256ull * 65792 + nBase + tx * 8;
    *reinterpret_cast<float4*>(bias)     = *reinterpret_cast<const float4*>(brow);
    *reinterpret_cast<float4*>(bias + 4) = *reinterpret_cast<const float4*>(brow + 4);

#pragma unroll
    for (int m = 0; m < 8; ++m) {
        float* orow = X + (size_t)(mBase + ty * 8 + m) * 65792 + nBase + tx * 8;
        float4 o0, o1;
        o0.x = c[m][0] + bias[0]; o0.y = c[m][1] + bias[1];
        o0.z = c[m][2] + bias[2]; o0.w = c[m][3] + bias[3];
        o1.x = c[m][4] + bias[4]; o1.y = c[m][5] + bias[5];
        o1.z = c[m][6] + bias[6]; o1.w = c[m][7] + bias[7];
        *reinterpret_cast<float4*>(orow)     = o0;
        *reinterpret_cast<float4*>(orow + 4) = o1;
    }
}

// ---------------------------------------------------------------------------
// K2: A[m][j,c] = sum_{b<256} l2[n,j,b] X1[m][b,c] + X1[m][256,c]
//     4096 batched GEMMs M=256, K=256, N=256 + bias.  grid (2, 2, 4096)
// ---------------------------------------------------------------------------
__global__ void __launch_bounds__(256, 2)
k_gemm2(const float* __restrict__ layer2)
{
    const int tid = threadIdx.x;
    const int ty = tid >> 4, tx = tid & 15;
    const int nt = blockIdx.x, mt = blockIdx.y;
    const int mz = blockIdx.z;
    const int m = mz >> 1, w = mz & 1;
    const int n = m >> 8;

    const float* __restrict__ X = (w ? g_X2 : g_X1) + (size_t)m * 65792;
    float* __restrict__ O       = (w ? g_B : g_A) + (size_t)m * 65536;
    const float* __restrict__ L2 = layer2 + (size_t)n * 65536;

    __shared__ float As[2][BK][BM];
    __shared__ float Bs[2][BK][BN];

    const int ar  = tid >> 1;
    const int kh  = (tid & 1) * 8;
    const int bkk = tid >> 4;
    const int bcq = (tid & 15) * 8;

    float va[8];
    float4 vb0, vb1;

    auto loadG = [&](int k0) {
        const float* ap = L2 + (size_t)(mt * BM + ar) * 256 + k0 + kh;
        *reinterpret_cast<float4*>(va)     = *reinterpret_cast<const float4*>(ap);
        *reinterpret_cast<float4*>(va + 4) = *reinterpret_cast<const float4*>(ap + 4);
        const float* bp = X + (size_t)(k0 + bkk) * 256 + nt * BN + bcq;
        vb0 = *reinterpret_cast<const float4*>(bp);
        vb1 = *reinterpret_cast<const float4*>(bp + 4);
    };
    auto stS = [&](int s) {
#pragma unroll
        for (int i = 0; i < 8; ++i) As[s][kh + i][ar] = va[i];
        *reinterpret_cast<float4*>(&Bs[s][bkk][bcq])     = vb0;
        *reinterpret_cast<float4*>(&Bs[s][bkk][bcq + 4]) = vb1;
    };

    unsigned long long acc[4][8];
#pragma unroll
    for (int u = 0; u < 4; ++u)
#pragma unroll
        for (int v = 0; v < 8; ++v) acc[u][v] = 0ull;

    loadG(0); stS(0); __syncthreads();
    for (int kt = 0; kt < NIT; ++kt) {
        if (kt + 1 < NIT) loadG((kt + 1) * BK);
        mm_tile16(acc, &As[kt & 1][0][0], &Bs[kt & 1][0][0], ty, tx);
        if (kt + 1 < NIT) { stS((kt + 1) & 1); __syncthreads(); }
    }

    float c[8][8];
    unpack_acc(c, acc);

    // bias: ones-column of l2p -> X1[m][b=256][c]
    float bias[8];
    const float* brow = X + 256ull * 256 + nt * BN + tx * 8;
    *reinterpret_cast<float4*>(bias)     = *reinterpret_cast<const float4*>(brow);
    *reinterpret_cast<float4*>(bias + 4) = *reinterpret_cast<const float4*>(brow + 4);

#pragma unroll
    for (int mm = 0; mm < 8; ++mm) {
        float* orow = O + (size_t)(mt * BM + ty * 8 + mm) * 256 + nt * BN + tx * 8;
        float4 o0, o1;
        o0.x = c[mm][0] + bias[0]; o0.y = c[mm][1] + bias[1];
        o0.z = c[mm][2] + bias[2]; o0.w = c[mm][3] + bias[3];
        o1.x = c[mm][4] + bias[4]; o1.y = c[mm][5] + bias[5];
        o1.z = c[mm][6] + bias[6]; o1.w = c[mm][7] + bias[7];
        *reinterpret_cast<float4*>(orow)     = o0;
        *reinterpret_cast<float4*>(orow + 4) = o1;
    }
}

// ---------------------------------------------------------------------------
// K3: per (m, jt):  T[j,c] = sum_d (B[m][j,d]*h2[d]) * W3T[d][c]
//     out[m][j] = sum_c (A[m][j,c]*h1[c]) * T[j,c]
//     grid (2048, 2); c processed in two 128-wide halves.
// ---------------------------------------------------------------------------
__global__ void __launch_bounds__(256, 2)
k_final(const float* __restrict__ h1,
        const float* __restrict__ h2,
        float* __restrict__ out)
{
    const int tid = threadIdx.x;
    const int ty = tid >> 4, tx = tid & 15;
    const int m = blockIdx.x, jt = blockIdx.y;

    __shared__ float As[2][BK][BM];
    __shared__ float Bs[2][BK][BN];
    __shared__ float h1s[256], h2s[256];
    __shared__ float red[16][128];

    h1s[tid] = h1[(size_t)m * 256 + tid];
    h2s[tid] = h2[(size_t)m * 256 + tid];
    __syncthreads();

    const float* __restrict__ Bm = g_B + (size_t)m * 65536 + (size_t)jt * 128 * 256;
    const float* __restrict__ Am = g_A + (size_t)m * 65536 + (size_t)jt * 128 * 256;

    float outp[8];
#pragma unroll
    for (int u = 0; u < 8; ++u) outp[u] = 0.0f;

    const int ar  = tid >> 1;
    const int kh  = (tid & 1) * 8;
    const int bkk = tid >> 4;
    const int bcq = (tid & 15) * 8;

    for (int ch = 0; ch < 2; ++ch) {
        unsigned long long acc[4][8];
#pragma unroll
        for (int u = 0; u < 4; ++u)
#pragma unroll
            for (int v = 0; v < 8; ++v) acc[u][v] = 0ull;

        float va[8];
        float4 vb0, vb1;

        auto loadG = [&](int k0) {
            int k = k0 + kh;
            const float* ap = Bm + (size_t)ar * 256 + k;
            float4 f0 = *reinterpret_cast<const float4*>(ap);
            float4 f1 = *reinterpret_cast<const float4*>(ap + 4);
            va[0] = f0.x * h2s[k];     va[1] = f0.y * h2s[k + 1];
            va[2] = f0.z * h2s[k + 2]; va[3] = f0.w * h2s[k + 3];
            va[4] = f1.x * h2s[k + 4]; va[5] = f1.y * h2s[k + 5];
            va[6] = f1.z * h2s[k + 6]; va[7] = f1.w * h2s[k + 7];
            const float* bp = g_W3T + (size_t)(k0 + bkk) * 256 + ch * 128 + bcq;
            vb0 = *reinterpret_cast<const float4*>(bp);
            vb1 = *reinterpret_cast<const float4*>(bp + 4);
        };
        auto stS = [&](int s) {
#pragma unroll
            for (int i = 0; i < 8; ++i) As[s][kh + i][ar] = va[i];
            *reinterpret_cast<float4*>(&Bs[s][bkk][bcq])     = vb0;
            *reinterpret_cast<float4*>(&Bs[s][bkk][bcq + 4]) = vb1;
        };

        loadG(0); stS(0); __syncthreads();
        for (int kt = 0; kt < NIT; ++kt) {
            if (kt + 1 < NIT) loadG((kt + 1) * BK);
            mm_tile16(acc, &As[kt & 1][0][0], &Bs[kt & 1][0][0], ty, tx);
            if (kt + 1 < NIT) { stS((kt + 1) & 1); __syncthreads(); }
        }

        float t[8][8];
        unpack_acc(t, acc);

        // epilogue: outp[j] += sum_c h1[c] * A[j,c] * T[j,c]
#pragma unroll
        for (int u = 0; u < 8; ++u) {
            const float* Arow = Am + (size_t)(ty * 8 + u) * 256 + ch * 128 + tx * 8;
            float4 a0 = *reinterpret_cast<const float4*>(Arow);
            float4 a1 = *reinterpret_cast<const float4*>(Arow + 4);
            int c0 = ch * 128 + tx * 8;
            outp[u] += a0.x * h1s[c0]     * t[u][0] + a0.y * h1s[c0 + 1] * t[u][1]
                     + a0.z * h1s[c0 + 2] * t[u][2] + a0.w * h1s[c0 + 3] * t[u][3]
                     + a1.x * h1s[c0 + 4] * t[u][4] + a1.y * h1s[c0 + 5] * t[u][5]
                     + a1.z * h1s[c0 + 6] * t[u][6] + a1.w * h1s[c0 + 7] * t[u][7];
        }
    }

    __syncthreads();
#pragma unroll
    for (int u = 0; u < 8; ++u)
        red[tx][ty * 8 + u] = outp[u];
    __syncthreads();

    if (tid < 128) {
        float s = 0.0f;
#pragma unroll
        for (int x = 0; x < 16; ++x) s += red[x][tid];
        out[(size_t)m * 256 + jt * 128 + tid] = s;
    }
}

// ---------------------------------------------------------------------------
extern "C" void kernel_launch(void* const* d_in, const int* in_sizes, int n_in,
                              void* d_out, int out_size)
{
    const float* layer1 = (const float*)d_in[0];
    const float* layer2 = (const float*)d_in[1];
    const float* h1     = (const float*)d_in[2];
    const float* h2     = (const float*)d_in[3];
    const float* W1     = (const float*)d_in[4];
    const float* W2     = (const float*)d_in[5];
    const float* W3     = (const float*)d_in[6];
    float* out = (float*)d_out;

    k_transpose<<<dim3(8, 8), dim3(32, 32)>>>(W3);
    k_gemm1<<<dim3(514, 16, 2), 256>>>(layer1, W1, W2);
    k_gemm2<<<dim3(2, 2, 4096), 256>>>(layer2);
    k_final<<<dim3(2048, 2), 256>>>(h1, h2, out);
}

// round 5
// speedup vs baseline: 1.4193x; 1.0005x over previous
#include <cuda_runtime.h>

// ---------------------------------------------------------------------------
// Triaffine:  out[n,i,j] = sum_{c,d} (h1[nic] * A[nijc]) * W3[c,d] * (h2[nid] * B[nijd])
//   A[nijc] = sum_{a,b} l1[nia] W1[abc] l2[njb]   (l1/l2 = [layer, ones])
//   B likewise with W2.
//
// v2: exact K=256 GEMMs (ones-column folded into an epilogue bias add),
// m-pair f32x2 accumulators (A pairs come free from LDS.128; B duplicated
// into (b,b) pairs with register MOVs instead of duplicated smem), BK=16.
// Crossbar traffic per 64 MACs/thread: 64B (was 96B) -> fma-pipe parity.
// ---------------------------------------------------------------------------

#define BM 128
#define BN 128
#define BK 16
#define NIT 16   // K = 256 exactly

// Scratch (module-load allocated; no runtime alloc)
__device__ __align__(16) float g_X1[2048ull * 257 * 256];
__device__ __align__(16) float g_X2[2048ull * 257 * 256];
__device__ __align__(16) float g_A [2048ull * 256 * 256];
__device__ __align__(16) float g_B [2048ull * 256 * 256];
__device__ __align__(16) float g_W3T[256 * 256];

// ---------------------------------------------------------------------------
// Inner 128x128 micro-step over BK k-slices.
// As: [BK][BM] plain.  Bs: [BK][BN] plain.
// acc[u][v] = packed pair (C[m0][n], C[m0+1][n]) with m0 = ty*8 + 2u,
// n = tx*8 + v.  A pairs are register-aliased halves of LDS.128 loads.
// ---------------------------------------------------------------------------
__device__ __forceinline__ void mm_tile16(unsigned long long acc[4][8],
                                          const float* __restrict__ As,
                                          const float* __restrict__ Bs,
                                          int ty, int tx)
{
#pragma unroll
    for (int kk = 0; kk < BK; ++kk) {
        ulonglong2 A0 = *reinterpret_cast<const ulonglong2*>(As + kk * BM + ty * 8);
        ulonglong2 A1 = *reinterpret_cast<const ulonglong2*>(As + kk * BM + ty * 8 + 4);
        unsigned long long ap[4];
        ap[0] = A0.x; ap[1] = A0.y; ap[2] = A1.x; ap[3] = A1.y;
        float4 b0 = *reinterpret_cast<const float4*>(Bs + kk * BN + tx * 8);
        float4 b1 = *reinterpret_cast<const float4*>(Bs + kk * BN + tx * 8 + 4);
        float bb[8];
        bb[0] = b0.x; bb[1] = b0.y; bb[2] = b0.z; bb[3] = b0.w;
        bb[4] = b1.x; bb[5] = b1.y; bb[6] = b1.z; bb[7] = b1.w;
#pragma unroll
        for (int v = 0; v < 8; ++v) {
            unsigned long long bp;
            asm("mov.b64 %0, {%1, %1};" : "=l"(bp) : "f"(bb[v]));
#pragma unroll
            for (int u = 0; u < 4; ++u)
                asm("fma.rn.f32x2 %0, %1, %2, %0;"
                    : "+l"(acc[u][v]) : "l"(ap[u]), "l"(bp));
        }
    }
}

__device__ __forceinline__ void unpack_acc(float c[8][8],
                                           const unsigned long long acc[4][8])
{
#pragma unroll
    for (int u = 0; u < 4; ++u)
#pragma unroll
        for (int v = 0; v < 8; ++v)
            asm("mov.b64 {%0, %1}, %2;"
                : "=f"(c[2 * u][v]), "=f"(c[2 * u + 1][v]) : "l"(acc[u][v]));
}

// ---------------------------------------------------------------------------
// K0: transpose W3 -> g_W3T
// ---------------------------------------------------------------------------
__global__ void k_transpose(const float* __restrict__ W3)
{
    __shared__ float t[32][33];
    int bx = blockIdx.x * 32, by = blockIdx.y * 32;
    t[threadIdx.y][threadIdx.x] = W3[(size_t)(by + threadIdx.y) * 256 + bx + threadIdx.x];
    __syncthreads();
    g_W3T[(size_t)(bx + threadIdx.y) * 256 + by + threadIdx.x] = t[threadIdx.x][threadIdx.y];
}

// ---------------------------------------------------------------------------
// K1: X{1,2}[m][bc] = sum_{a<256} l1[m,a] W{1,2}[a][bc] + W{1,2}[256][bc]
//     GEMM M=2048, K=256, N=65792 + bias.  grid (514, 16, 2)
// ---------------------------------------------------------------------------
__global__ void __launch_bounds__(256, 2)
k_gemm1(const float* __restrict__ layer1,
        const float* __restrict__ W1,
        const float* __restrict__ W2)
{
    const int tid = threadIdx.x;
    const int ty = tid >> 4, tx = tid & 15;
    const int nBase = blockIdx.x * BN;
    const int mBase = blockIdx.y * BM;
    const float* __restrict__ W = blockIdx.z ? W2 : W1;
    float* __restrict__ X = blockIdx.z ? g_X2 : g_X1;

    __shared__ float As[2][BK][BM];
    __shared__ float Bs[2][BK][BN];

    const int ar  = tid >> 1;           // A row within tile (0..127)
    const int kh  = (tid & 1) * 8;      // A k offset {0, 8}
    const int bkk = tid >> 4;           // B k row (0..15)
    const int bcq = (tid & 15) * 8;     // B col offset

    float va[8];
    float4 vb0, vb1;

    auto loadG = [&](int k0) {
        const float* ap = layer1 + (size_t)(mBase + ar) * 256 + k0 + kh;
        *reinterpret_cast<float4*>(va)     = *reinterpret_cast<const float4*>(ap);
        *reinterpret_cast<float4*>(va + 4) = *reinterpret_cast<const float4*>(ap + 4);
        const float* bp = W + (size_t)(k0 + bkk) * 65792 + nBase + bcq;
        vb0 = *reinterpret_cast<const float4*>(bp);
        vb1 = *reinterpret_cast<const float4*>(bp + 4);
    };
    auto stS = [&](int s) {
#pragma unroll
        for (int i = 0; i < 8; ++i) As[s][kh + i][ar] = va[i];
        *reinterpret_cast<float4*>(&Bs[s][bkk][bcq])     = vb0;
        *reinterpret_cast<float4*>(&Bs[s][bkk][bcq + 4]) = vb1;
    };

    unsigned long long acc[4][8];
#pragma unroll
    for (int u = 0; u < 4; ++u)
#pragma unroll
        for (int v = 0; v < 8; ++v) acc[u][v] = 0ull;

    loadG(0); stS(0); __syncthreads();
    for (int kt = 0; kt < NIT; ++kt) {
        if (kt + 1 < NIT) loadG((kt + 1) * BK);
        mm_tile16(acc, &As[kt & 1][0][0], &Bs[kt & 1][0][0], ty, tx);
        if (kt + 1 < NIT) { stS((kt + 1) & 1); __syncthreads(); }
    }

    float c[8][8];
    unpack_acc(c, acc);

    // bias: ones-column contribution = W[256][col]
    float bias[8];
    const float* brow = W + 256ull * 65792 + nBase + tx * 8;
    *reinterpret_cast<float4*>(bias)     = *reinterpret_cast<const float4*>(brow);
    *reinterpret_cast<float4*>(bias + 4) = *reinterpret_cast<const float4*>(brow + 4);

#pragma unroll
    for (int m = 0; m < 8; ++m) {
        float* orow = X + (size_t)(mBase + ty * 8 + m) * 65792 + nBase + tx * 8;
        float4 o0, o1;
        o0.x = c[m][0] + bias[0]; o0.y = c[m][1] + bias[1];
        o0.z = c[m][2] + bias[2]; o0.w = c[m][3] + bias[3];
        o1.x = c[m][4] + bias[4]; o1.y = c[m][5] + bias[5];
        o1.z = c[m][6] + bias[6]; o1.w = c[m][7] + bias[7];
        *reinterpret_cast<float4*>(orow)     = o0;
        *reinterpret_cast<float4*>(orow + 4) = o1;
    }
}

// ---------------------------------------------------------------------------
// K2: A[m][j,c] = sum_{b<256} l2[n,j,b] X1[m][b,c] + X1[m][256,c]
//     4096 batched GEMMs M=256, K=256, N=256 + bias.  grid (2, 2, 4096)
// ---------------------------------------------------------------------------
__global__ void __launch_bounds__(256, 2)
k_gemm2(const float* __restrict__ layer2)
{
    const int tid = threadIdx.x;
    const int ty = tid >> 4, tx = tid & 15;
    const int nt = blockIdx.x, mt = blockIdx.y;
    const int mz = blockIdx.z;
    const int m = mz >> 1, w = mz & 1;
    const int n = m >> 8;

    const float* __restrict__ X = (w ? g_X2 : g_X1) + (size_t)m * 65792;
    float* __restrict__ O       = (w ? g_B : g_A) + (size_t)m * 65536;
    const float* __restrict__ L2 = layer2 + (size_t)n * 65536;

    __shared__ float As[2][BK][BM];
    __shared__ float Bs[2][BK][BN];

    const int ar  = tid >> 1;
    const int kh  = (tid & 1) * 8;
    const int bkk = tid >> 4;
    const int bcq = (tid & 15) * 8;

    float va[8];
    float4 vb0, vb1;

    auto loadG = [&](int k0) {
        const float* ap = L2 + (size_t)(mt * BM + ar) * 256 + k0 + kh;
        *reinterpret_cast<float4*>(va)     = *reinterpret_cast<const float4*>(ap);
        *reinterpret_cast<float4*>(va + 4) = *reinterpret_cast<const float4*>(ap + 4);
        const float* bp = X + (size_t)(k0 + bkk) * 256 + nt * BN + bcq;
        vb0 = *reinterpret_cast<const float4*>(bp);
        vb1 = *reinterpret_cast<const float4*>(bp + 4);
    };
    auto stS = [&](int s) {
#pragma unroll
        for (int i = 0; i < 8; ++i) As[s][kh + i][ar] = va[i];
        *reinterpret_cast<float4*>(&Bs[s][bkk][bcq])     = vb0;
        *reinterpret_cast<float4*>(&Bs[s][bkk][bcq + 4]) = vb1;
    };

    unsigned long long acc[4][8];
#pragma unroll
    for (int u = 0; u < 4; ++u)
#pragma unroll
        for (int v = 0; v < 8; ++v) acc[u][v] = 0ull;

    loadG(0); stS(0); __syncthreads();
    for (int kt = 0; kt < NIT; ++kt) {
        if (kt + 1 < NIT) loadG((kt + 1) * BK);
        mm_tile16(acc, &As[kt & 1][0][0], &Bs[kt & 1][0][0], ty, tx);
        if (kt + 1 < NIT) { stS((kt + 1) & 1); __syncthreads(); }
    }

    float c[8][8];
    unpack_acc(c, acc);

    // bias: ones-column of l2p -> X1[m][b=256][c]
    float bias[8];
    const float* brow = X + 256ull * 256 + nt * BN + tx * 8;
    *reinterpret_cast<float4*>(bias)     = *reinterpret_cast<const float4*>(brow);
    *reinterpret_cast<float4*>(bias + 4) = *reinterpret_cast<const float4*>(brow + 4);

#pragma unroll
    for (int mm = 0; mm < 8; ++mm) {
        float* orow = O + (size_t)(mt * BM + ty * 8 + mm) * 256 + nt * BN + tx * 8;
        float4 o0, o1;
        o0.x = c[mm][0] + bias[0]; o0.y = c[mm][1] + bias[1];
        o0.z = c[mm][2] + bias[2]; o0.w = c[mm][3] + bias[3];
        o1.x = c[mm][4] + bias[4]; o1.y = c[mm][5] + bias[5];
        o1.z = c[mm][6] + bias[6]; o1.w = c[mm][7] + bias[7];
        *reinterpret_cast<float4*>(orow)     = o0;
        *reinterpret_cast<float4*>(orow + 4) = o1;
    }
}

// ---------------------------------------------------------------------------
// K3: per (m, jt):  T[j,c] = sum_d (B[m][j,d]*h2[d]) * W3T[d][c]
//     out[m][j] = sum_c (A[m][j,c]*h1[c]) * T[j,c]
//     grid (2048, 2); c processed in two 128-wide halves.
// ---------------------------------------------------------------------------
__global__ void __launch_bounds__(256, 2)
k_final(const float* __restrict__ h1,
        const float* __restrict__ h2,
        float* __restrict__ out)
{
    const int tid = threadIdx.x;
    const int ty = tid >> 4, tx = tid & 15;
    const int m = blockIdx.x, jt = blockIdx.y;

    __shared__ float As[2][BK][BM];
    __shared__ float Bs[2][BK][BN];
    __shared__ float h1s[256], h2s[256];
    __shared__ float red[16][128];

    h1s[tid] = h1[(size_t)m * 256 + tid];
    h2s[tid] = h2[(size_t)m * 256 + tid];
    __syncthreads();

    const float* __restrict__ Bm = g_B + (size_t)m * 65536 + (size_t)jt * 128 * 256;
    const float* __restrict__ Am = g_A + (size_t)m * 65536 + (size_t)jt * 128 * 256;

    float outp[8];
#pragma unroll
    for (int u = 0; u < 8; ++u) outp[u] = 0.0f;

    const int ar  = tid >> 1;
    const int kh  = (tid & 1) * 8;
    const int bkk = tid >> 4;
    const int bcq = (tid & 15) * 8;

    for (int ch = 0; ch < 2; ++ch) {
        unsigned long long acc[4][8];
#pragma unroll
        for (int u = 0; u < 4; ++u)
#pragma unroll
            for (int v = 0; v < 8; ++v) acc[u][v] = 0ull;

        float va[8];
        float4 vb0, vb1;

        auto loadG = [&](int k0) {
            int k = k0 + kh;
            const float* ap = Bm + (size_t)ar * 256 + k;
            float4 f0 = *reinterpret_cast<const float4*>(ap);
            float4 f1 = *reinterpret_cast<const float4*>(ap + 4);
            va[0] = f0.x * h2s[k];     va[1] = f0.y * h2s[k + 1];
            va[2] = f0.z * h2s[k + 2]; va[3] = f0.w * h2s[k + 3];
            va[4] = f1.x * h2s[k + 4]; va[5] = f1.y * h2s[k + 5];
            va[6] = f1.z * h2s[k + 6]; va[7] = f1.w * h2s[k + 7];
            const float* bp = g_W3T + (size_t)(k0 + bkk) * 256 + ch * 128 + bcq;
            vb0 = *reinterpret_cast<const float4*>(bp);
            vb1 = *reinterpret_cast<const float4*>(bp + 4);
        };
        auto stS = [&](int s) {
#pragma unroll
            for (int i = 0; i < 8; ++i) As[s][kh + i][ar] = va[i];
            *reinterpret_cast<float4*>(&Bs[s][bkk][bcq])     = vb0;
            *reinterpret_cast<float4*>(&Bs[s][bkk][bcq + 4]) = vb1;
        };

        loadG(0); stS(0); __syncthreads();
        for (int kt = 0; kt < NIT; ++kt) {
            if (kt + 1 < NIT) loadG((kt + 1) * BK);
            mm_tile16(acc, &As[kt & 1][0][0], &Bs[kt & 1][0][0], ty, tx);
            if (kt + 1 < NIT) { stS((kt + 1) & 1); __syncthreads(); }
        }

        float t[8][8];
        unpack_acc(t, acc);

        // epilogue: outp[j] += sum_c h1[c] * A[j,c] * T[j,c]
#pragma unroll
        for (int u = 0; u < 8; ++u) {
            const float* Arow = Am + (size_t)(ty * 8 + u) * 256 + ch * 128 + tx * 8;
            float4 a0 = *reinterpret_cast<const float4*>(Arow);
            float4 a1 = *reinterpret_cast<const float4*>(Arow + 4);
            int c0 = ch * 128 + tx * 8;
            outp[u] += a0.x * h1s[c0]     * t[u][0] + a0.y * h1s[c0 + 1] * t[u][1]
                     + a0.z * h1s[c0 + 2] * t[u][2] + a0.w * h1s[c0 + 3] * t[u][3]
                     + a1.x * h1s[c0 + 4] * t[u][4] + a1.y * h1s[c0 + 5] * t[u][5]
                     + a1.z * h1s[c0 + 6] * t[u][6] + a1.w * h1s[c0 + 7] * t[u][7];
        }
    }

    __syncthreads();
#pragma unroll
    for (int u = 0; u < 8; ++u)
        red[tx][ty * 8 + u] = outp[u];
    __syncthreads();

    if (tid < 128) {
        float s = 0.0f;
#pragma unroll
        for (int x = 0; x < 16; ++x) s += red[x][tid];
        out[(size_t)m * 256 + jt * 128 + tid] = s;
    }
}

// ---------------------------------------------------------------------------
extern "C" void kernel_launch(void* const* d_in, const int* in_sizes, int n_in,
                              void* d_out, int out_size)
{
    const float* layer1 = (const float*)d_in[0];
    const float* layer2 = (const float*)d_in[1];
    const float* h1     = (const float*)d_in[2];
    const float* h2     = (const float*)d_in[3];
    const float* W1     = (const float*)d_in[4];
    const float* W2     = (const float*)d_in[5];
    const float* W3     = (const float*)d_in[6];
    float* out = (float*)d_out;

    k_transpose<<<dim3(8, 8), dim3(32, 32)>>>(W3);
    k_gemm1<<<dim3(514, 16, 2), 256>>>(layer1, W1, W2);
    k_gemm2<<<dim3(2, 2, 4096), 256>>>(layer2);
    k_final<<<dim3(2048, 2), 256>>>(h1, h2, out);
}